// round 7
// baseline (speedup 1.0000x reference)
#include <cuda_runtime.h>
#include <cuda_bf16.h>
#include <math.h>

// FactorizedPrior: z_hat = round(z); likelihoods = clip(cdf(z_hat+0.5)-cdf(z_hat-0.5), 1e-9)
// cdf = sigmoid( 4-layer per-channel tiny MLP with softplus'd weights ).
// With factors f==0 (the dataset), the MLP collapses to logit = a[c]*x + d[c].
// SINGLE fused kernel: every block recomputes the 192-entry affine table into
// shared memory (fast-math, ~0.3us), then streams. One wave (148 SMs x 5 blocks),
// software-pipelined loads, evict-first ld/st.

#define NCH 192
#define NB 32
#define NHW 4096                 // 64*64
#define NELEM (NB * NCH * NHW)   // 25165824
#define N4 (NELEM / 4)           // 6291456 float4s (divisible by 512)
#define GRID_MAIN 740            // 148 SMs * 5 blocks -> one resident wave
#define CHUNK (GRID_MAIN * 512)  // float4s consumed per grid sweep (ILP=2)

__device__ __forceinline__ float softplus_fast(float x) {
    // log(1+e^x) = max(x,0) + log(1+e^-|x|), fast-math MUFU version.
    float e = __expf(-fabsf(x));
    return fmaxf(x, 0.f) + __logf(1.f + e);
}

// ---------------- general (f != 0) fallback: precise, per-element, dead with
// the dataset inputs; isolated from the fast path's register allocation. -----
__device__ __noinline__ float cdf_raw(int c, float x,
                                      const float* m0, const float* m1,
                                      const float* m2, const float* m3,
                                      const float* b0, const float* b1,
                                      const float* b2, const float* b3,
                                      const float* f0, const float* f1,
                                      const float* f2) {
    float v[3], u[3];
    #pragma unroll
    for (int r = 0; r < 3; r++) {
        float w = (m0[c*3+r] > 0.f) ? m0[c*3+r] + log1pf(expf(-m0[c*3+r])) : log1pf(expf(m0[c*3+r]));
        v[r] = fmaf(w, x, b0[c*3+r]);
        v[r] = fmaf(tanhf(f0[c*3+r]), tanhf(v[r]), v[r]);
    }
    #pragma unroll
    for (int r = 0; r < 3; r++) {
        u[r] = b1[c*3+r];
        #pragma unroll
        for (int k = 0; k < 3; k++) {
            float m = m1[c*9 + r*3 + k];
            float w = (m > 0.f) ? m + log1pf(expf(-m)) : log1pf(expf(m));
            u[r] = fmaf(w, v[k], u[r]);
        }
        u[r] = fmaf(tanhf(f1[c*3+r]), tanhf(u[r]), u[r]);
    }
    #pragma unroll
    for (int r = 0; r < 3; r++) {
        v[r] = b2[c*3+r];
        #pragma unroll
        for (int k = 0; k < 3; k++) {
            float m = m2[c*9 + r*3 + k];
            float w = (m > 0.f) ? m + log1pf(expf(-m)) : log1pf(expf(m));
            v[r] = fmaf(w, u[k], v[r]);
        }
        v[r] = fmaf(tanhf(f2[c*3+r]), tanhf(v[r]), v[r]);
    }
    float l = b3[c];
    #pragma unroll
    for (int k = 0; k < 3; k++) {
        float m = m3[c*3+k];
        float w = (m > 0.f) ? m + log1pf(expf(-m)) : log1pf(expf(m));
        l = fmaf(w, v[k], l);
    }
    return 1.f / (1.f + expf(-l));
}

__device__ __forceinline__ void affine_quad(float4 zv, float4 p, float4& zh, float4& lk) {
    #pragma unroll
    for (int j = 0; j < 4; j++) {
        float x  = rintf((&zv.x)[j]);                  // round half-to-even == jnp.round
        float t  = fmaf(p.x, x, p.y);
        float E  = __expf(-(t + p.w));                 // e^{-(t+h)}
        float up = __fdividef(1.f, 1.f + E);           // sigmoid(t+h)
        float lo = __fdividef(1.f, fmaf(E, p.z, 1.f)); // sigmoid(t-h): e^{-(t-h)} = E*e^{a}
        (&zh.x)[j] = x;
        (&lk.x)[j] = fmaxf(up - lo, 1e-9f);
    }
}

__global__ void __launch_bounds__(256, 5) fp_fused_kernel(
        const float4* __restrict__ z, float* __restrict__ out,
        const float* __restrict__ m0, const float* __restrict__ m1,
        const float* __restrict__ m2, const float* __restrict__ m3,
        const float* __restrict__ b0, const float* __restrict__ b1,
        const float* __restrict__ b2, const float* __restrict__ b3,
        const float* __restrict__ f0, const float* __restrict__ f1,
        const float* __restrict__ f2) {
    __shared__ float4 s_ad[NCH];   // {a, d, exp(a), 0.5a}

    int tid   = threadIdx.x;
    int base0 = blockIdx.x * 512 + tid;

    // Kick off the first z tile BEFORE touching params: DRAM starts streaming
    // while this block computes its affine table.
    float4 zv0 = __ldcs(z + base0);
    float4 zv1 = __ldcs(z + base0 + 256);

    // ---- per-block affine table (one channel per thread) ----
    int nz = 0;
    if (tid < NCH) {
        int c = tid;
        float w0[3], W1[9], W2[9], w3[3];
        #pragma unroll
        for (int i = 0; i < 3; i++) w0[i] = softplus_fast(m0[c * 3 + i]);
        #pragma unroll
        for (int i = 0; i < 9; i++) W1[i] = softplus_fast(m1[c * 9 + i]);
        #pragma unroll
        for (int i = 0; i < 9; i++) W2[i] = softplus_fast(m2[c * 9 + i]);
        #pragma unroll
        for (int i = 0; i < 3; i++) w3[i] = softplus_fast(m3[c * 3 + i]);

        #pragma unroll
        for (int i = 0; i < 3; i++) nz |= (f0[c * 3 + i] != 0.f);
        #pragma unroll
        for (int i = 0; i < 3; i++) nz |= (f1[c * 3 + i] != 0.f);
        #pragma unroll
        for (int i = 0; i < 3; i++) nz |= (f2[c * 3 + i] != 0.f);

        float va[3], vd[3];
        #pragma unroll
        for (int i = 0; i < 3; i++) { va[i] = w0[i]; vd[i] = b0[c * 3 + i]; }

        float ta[3], td[3];
        #pragma unroll
        for (int r = 0; r < 3; r++) {
            ta[r] = W1[r*3+0]*va[0] + W1[r*3+1]*va[1] + W1[r*3+2]*va[2];
            td[r] = W1[r*3+0]*vd[0] + W1[r*3+1]*vd[1] + W1[r*3+2]*vd[2] + b1[c*3+r];
        }
        #pragma unroll
        for (int r = 0; r < 3; r++) {
            va[r] = W2[r*3+0]*ta[0] + W2[r*3+1]*ta[1] + W2[r*3+2]*ta[2];
            vd[r] = W2[r*3+0]*td[0] + W2[r*3+1]*td[1] + W2[r*3+2]*td[2] + b2[c*3+r];
        }
        float a = w3[0]*va[0] + w3[1]*va[1] + w3[2]*va[2];
        float d = w3[0]*vd[0] + w3[1]*vd[1] + w3[2]*vd[2] + b3[c];

        s_ad[c] = make_float4(a, d, __expf(a), 0.5f * a);
    }
    int flag = __syncthreads_or(nz);   // barrier also publishes s_ad

    float4* out_zh = reinterpret_cast<float4*>(out);
    float4* out_lk = reinterpret_cast<float4*>(out + NELEM);

    // ---- streaming loop, software-pipelined (prefetch next tile) ----
    for (int base = base0; base < N4; base += CHUNK) {
        int nbase = base + CHUNK;
        float4 nz0, nz1;
        if (nbase < N4) {                 // N4 % 512 == 0 -> nbase+256 also in range
            nz0 = __ldcs(z + nbase);
            nz1 = __ldcs(z + nbase + 256);
        }

        int c0 = (base >> 10) % NCH;          // 1024 float4 per (b,c) plane
        int c1 = ((base + 256) >> 10) % NCH;  // warp-uniform -> smem broadcast

        float4 zh0, lk0, zh1, lk1;
        if (flag == 0) {
            affine_quad(zv0, s_ad[c0], zh0, lk0);
            affine_quad(zv1, s_ad[c1], zh1, lk1);
        } else {
            #pragma unroll
            for (int j = 0; j < 4; j++) {
                float x0 = rintf((&zv0.x)[j]);
                (&zh0.x)[j] = x0;
                (&lk0.x)[j] = fmaxf(cdf_raw(c0, x0+0.5f, m0,m1,m2,m3,b0,b1,b2,b3,f0,f1,f2)
                                  - cdf_raw(c0, x0-0.5f, m0,m1,m2,m3,b0,b1,b2,b3,f0,f1,f2), 1e-9f);
                float x1 = rintf((&zv1.x)[j]);
                (&zh1.x)[j] = x1;
                (&lk1.x)[j] = fmaxf(cdf_raw(c1, x1+0.5f, m0,m1,m2,m3,b0,b1,b2,b3,f0,f1,f2)
                                  - cdf_raw(c1, x1-0.5f, m0,m1,m2,m3,b0,b1,b2,b3,f0,f1,f2), 1e-9f);
            }
        }

        __stcs(out_zh + base, zh0);
        __stcs(out_zh + base + 256, zh1);
        __stcs(out_lk + base, lk0);
        __stcs(out_lk + base + 256, lk1);

        zv0 = nz0;
        zv1 = nz1;
    }
}

extern "C" void kernel_launch(void* const* d_in, const int* in_sizes, int n_in,
                              void* d_out, int out_size) {
    const float* z  = (const float*)d_in[0];
    const float* m0 = (const float*)d_in[1];
    const float* m1 = (const float*)d_in[2];
    const float* m2 = (const float*)d_in[3];
    const float* m3 = (const float*)d_in[4];
    const float* b0 = (const float*)d_in[5];
    const float* b1 = (const float*)d_in[6];
    const float* b2 = (const float*)d_in[7];
    const float* b3 = (const float*)d_in[8];
    const float* f0 = (const float*)d_in[9];
    const float* f1 = (const float*)d_in[10];
    const float* f2 = (const float*)d_in[11];

    fp_fused_kernel<<<GRID_MAIN, 256>>>((const float4*)z, (float*)d_out,
                                        m0, m1, m2, m3, b0, b1, b2, b3, f0, f1, f2);
}

// round 8
// speedup vs baseline: 1.1027x; 1.1027x over previous
#include <cuda_runtime.h>
#include <cuda_bf16.h>
#include <math.h>

// FactorizedPrior: z_hat = round(z); likelihoods = clip(cdf(z_hat+0.5)-cdf(z_hat-0.5), 1e-9)
// cdf = sigmoid( 4-layer per-channel tiny MLP with softplus'd weights ).
// With factors f==0 (the dataset), the MLP collapses to logit = a[c]*x + d[c].
// Single fused kernel; every block builds the 192-entry affine table in smem
// (fast-math, overlapped, params L2-resident), then runs the R5-proven simple
// streaming loop: grid 2368x256, ILP=2, evict-first ld/st, no sw pipeline.

#define NCH 192
#define NB 32
#define NHW 4096                 // 64*64
#define NELEM (NB * NCH * NHW)   // 25165824
#define N4 (NELEM / 4)           // 6291456 float4s (divisible by 512)
#define GRID_MAIN 2368           // 148 SMs * 16 blocks (R5-proven geometry)
#define CHUNK (GRID_MAIN * 512)  // float4s consumed per grid sweep (ILP=2)

__device__ __forceinline__ float softplus_fast(float x) {
    // log(1+e^x) = max(x,0) + log(1+e^-|x|), fast-math MUFU version.
    float e = __expf(-fabsf(x));
    return fmaxf(x, 0.f) + __logf(1.f + e);
}

// ---------------- general (f != 0) fallback: precise, per-element, dead with
// the dataset inputs; isolated from the fast path's register allocation. -----
__device__ __noinline__ float cdf_raw(int c, float x,
                                      const float* m0, const float* m1,
                                      const float* m2, const float* m3,
                                      const float* b0, const float* b1,
                                      const float* b2, const float* b3,
                                      const float* f0, const float* f1,
                                      const float* f2) {
    float v[3], u[3];
    #pragma unroll
    for (int r = 0; r < 3; r++) {
        float w = (m0[c*3+r] > 0.f) ? m0[c*3+r] + log1pf(expf(-m0[c*3+r])) : log1pf(expf(m0[c*3+r]));
        v[r] = fmaf(w, x, b0[c*3+r]);
        v[r] = fmaf(tanhf(f0[c*3+r]), tanhf(v[r]), v[r]);
    }
    #pragma unroll
    for (int r = 0; r < 3; r++) {
        u[r] = b1[c*3+r];
        #pragma unroll
        for (int k = 0; k < 3; k++) {
            float m = m1[c*9 + r*3 + k];
            float w = (m > 0.f) ? m + log1pf(expf(-m)) : log1pf(expf(m));
            u[r] = fmaf(w, v[k], u[r]);
        }
        u[r] = fmaf(tanhf(f1[c*3+r]), tanhf(u[r]), u[r]);
    }
    #pragma unroll
    for (int r = 0; r < 3; r++) {
        v[r] = b2[c*3+r];
        #pragma unroll
        for (int k = 0; k < 3; k++) {
            float m = m2[c*9 + r*3 + k];
            float w = (m > 0.f) ? m + log1pf(expf(-m)) : log1pf(expf(m));
            v[r] = fmaf(w, u[k], v[r]);
        }
        v[r] = fmaf(tanhf(f2[c*3+r]), tanhf(v[r]), v[r]);
    }
    float l = b3[c];
    #pragma unroll
    for (int k = 0; k < 3; k++) {
        float m = m3[c*3+k];
        float w = (m > 0.f) ? m + log1pf(expf(-m)) : log1pf(expf(m));
        l = fmaf(w, v[k], l);
    }
    return 1.f / (1.f + expf(-l));
}

__device__ __forceinline__ void affine_quad(float4 zv, float4 p, float4& zh, float4& lk) {
    #pragma unroll
    for (int j = 0; j < 4; j++) {
        float x  = rintf((&zv.x)[j]);                  // round half-to-even == jnp.round
        float t  = fmaf(p.x, x, p.y);
        float E  = __expf(-(t + p.w));                 // e^{-(t+h)}
        float up = __fdividef(1.f, 1.f + E);           // sigmoid(t+h)
        float lo = __fdividef(1.f, fmaf(E, p.z, 1.f)); // sigmoid(t-h): e^{-(t-h)} = E*e^{a}
        (&zh.x)[j] = x;
        (&lk.x)[j] = fmaxf(up - lo, 1e-9f);
    }
}

__global__ void __launch_bounds__(256, 5) fp_fused_kernel(
        const float4* __restrict__ z, float* __restrict__ out,
        const float* __restrict__ m0, const float* __restrict__ m1,
        const float* __restrict__ m2, const float* __restrict__ m3,
        const float* __restrict__ b0, const float* __restrict__ b1,
        const float* __restrict__ b2, const float* __restrict__ b3,
        const float* __restrict__ f0, const float* __restrict__ f1,
        const float* __restrict__ f2) {
    __shared__ float4 s_ad[NCH];   // {a, d, exp(a), 0.5a}

    int tid = threadIdx.x;

    // ---- per-block affine table (one channel per thread), L2-resident params ----
    int nz = 0;
    if (tid < NCH) {
        int c = tid;
        float w0[3], W1[9], W2[9], w3[3];
        #pragma unroll
        for (int i = 0; i < 3; i++) w0[i] = softplus_fast(m0[c * 3 + i]);
        #pragma unroll
        for (int i = 0; i < 9; i++) W1[i] = softplus_fast(m1[c * 9 + i]);
        #pragma unroll
        for (int i = 0; i < 9; i++) W2[i] = softplus_fast(m2[c * 9 + i]);
        #pragma unroll
        for (int i = 0; i < 3; i++) w3[i] = softplus_fast(m3[c * 3 + i]);

        #pragma unroll
        for (int i = 0; i < 3; i++) nz |= (f0[c * 3 + i] != 0.f);
        #pragma unroll
        for (int i = 0; i < 3; i++) nz |= (f1[c * 3 + i] != 0.f);
        #pragma unroll
        for (int i = 0; i < 3; i++) nz |= (f2[c * 3 + i] != 0.f);

        float va[3], vd[3];
        #pragma unroll
        for (int i = 0; i < 3; i++) { va[i] = w0[i]; vd[i] = b0[c * 3 + i]; }

        float ta[3], td[3];
        #pragma unroll
        for (int r = 0; r < 3; r++) {
            ta[r] = W1[r*3+0]*va[0] + W1[r*3+1]*va[1] + W1[r*3+2]*va[2];
            td[r] = W1[r*3+0]*vd[0] + W1[r*3+1]*vd[1] + W1[r*3+2]*vd[2] + b1[c*3+r];
        }
        #pragma unroll
        for (int r = 0; r < 3; r++) {
            va[r] = W2[r*3+0]*ta[0] + W2[r*3+1]*ta[1] + W2[r*3+2]*ta[2];
            vd[r] = W2[r*3+0]*td[0] + W2[r*3+1]*td[1] + W2[r*3+2]*td[2] + b2[c*3+r];
        }
        float a = w3[0]*va[0] + w3[1]*va[1] + w3[2]*va[2];
        float d = w3[0]*vd[0] + w3[1]*vd[1] + w3[2]*vd[2] + b3[c];

        s_ad[c] = make_float4(a, d, __expf(a), 0.5f * a);
    }
    int flag = __syncthreads_or(nz);   // barrier also publishes s_ad

    float4* out_zh = reinterpret_cast<float4*>(out);
    float4* out_lk = reinterpret_cast<float4*>(out + NELEM);

    // ---- streaming loop: exact R5 structure (simple, no sw pipeline) ----
    for (int base = blockIdx.x * 512 + tid; base < N4; base += CHUNK) {
        int i0 = base;
        int i1 = base + 256;          // always < N4 (N4 % 512 == 0)
        int c0 = (i0 >> 10) % NCH;    // 1024 float4 per (b,c) plane
        int c1 = (i1 >> 10) % NCH;    // warp-uniform -> smem broadcast

        float4 zv0 = __ldcs(z + i0);
        float4 zv1 = __ldcs(z + i1);
        float4 zh0, lk0, zh1, lk1;

        if (flag == 0) {
            affine_quad(zv0, s_ad[c0], zh0, lk0);
            affine_quad(zv1, s_ad[c1], zh1, lk1);
        } else {
            #pragma unroll
            for (int j = 0; j < 4; j++) {
                float x0 = rintf((&zv0.x)[j]);
                (&zh0.x)[j] = x0;
                (&lk0.x)[j] = fmaxf(cdf_raw(c0, x0+0.5f, m0,m1,m2,m3,b0,b1,b2,b3,f0,f1,f2)
                                  - cdf_raw(c0, x0-0.5f, m0,m1,m2,m3,b0,b1,b2,b3,f0,f1,f2), 1e-9f);
                float x1 = rintf((&zv1.x)[j]);
                (&zh1.x)[j] = x1;
                (&lk1.x)[j] = fmaxf(cdf_raw(c1, x1+0.5f, m0,m1,m2,m3,b0,b1,b2,b3,f0,f1,f2)
                                  - cdf_raw(c1, x1-0.5f, m0,m1,m2,m3,b0,b1,b2,b3,f0,f1,f2), 1e-9f);
            }
        }

        __stcs(out_zh + i0, zh0);
        __stcs(out_zh + i1, zh1);
        __stcs(out_lk + i0, lk0);
        __stcs(out_lk + i1, lk1);
    }
}

extern "C" void kernel_launch(void* const* d_in, const int* in_sizes, int n_in,
                              void* d_out, int out_size) {
    const float* z  = (const float*)d_in[0];
    const float* m0 = (const float*)d_in[1];
    const float* m1 = (const float*)d_in[2];
    const float* m2 = (const float*)d_in[3];
    const float* m3 = (const float*)d_in[4];
    const float* b0 = (const float*)d_in[5];
    const float* b1 = (const float*)d_in[6];
    const float* b2 = (const float*)d_in[7];
    const float* b3 = (const float*)d_in[8];
    const float* f0 = (const float*)d_in[9];
    const float* f1 = (const float*)d_in[10];
    const float* f2 = (const float*)d_in[11];

    fp_fused_kernel<<<GRID_MAIN, 256>>>((const float4*)z, (float*)d_out,
                                        m0, m1, m2, m3, b0, b1, b2, b3, f0, f1, f2);
}

// round 11
// speedup vs baseline: 1.1344x; 1.0287x over previous
#include <cuda_runtime.h>
#include <cuda_bf16.h>
#include <math.h>

// FactorizedPrior: z_hat = round(z); likelihoods = clip(cdf(z_hat+0.5)-cdf(z_hat-0.5), 1e-9)
// cdf = sigmoid( 4-layer per-channel tiny MLP with softplus'd weights ).
// With factors f==0 (the dataset), the MLP collapses to logit = a[c]*x + d[c].
// Single fused kernel; every block builds the 192-entry affine table in smem,
// then streams (grid 2368x256, ILP=2, evict-first ld/st).
// R9: regs capped via __launch_bounds__(256,6) to restore 6 blocks/SM, and the
// sigmoid difference computed in one divide:
//   up - lo = E*(K-1) / ((1+E)*(1+E*K)),  E=e^{-(t+h)}, K=e^{a}>1.

#define NCH 192
#define NB 32
#define NHW 4096                 // 64*64
#define NELEM (NB * NCH * NHW)   // 25165824
#define N4 (NELEM / 4)           // 6291456 float4s (divisible by 512)
#define GRID_MAIN 2368           // 148 SMs * 16 blocks
#define CHUNK (GRID_MAIN * 512)  // float4s consumed per grid sweep (ILP=2)

__device__ __forceinline__ float softplus_fast(float x) {
    // log(1+e^x) = max(x,0) + log(1+e^-|x|), fast-math MUFU version.
    float e = __expf(-fabsf(x));
    return fmaxf(x, 0.f) + __logf(1.f + e);
}

// ---------------- general (f != 0) fallback: precise, per-element, dead with
// the dataset inputs; isolated from the fast path's register allocation. -----
__device__ __noinline__ float cdf_raw(int c, float x,
                                      const float* m0, const float* m1,
                                      const float* m2, const float* m3,
                                      const float* b0, const float* b1,
                                      const float* b2, const float* b3,
                                      const float* f0, const float* f1,
                                      const float* f2) {
    float v[3], u[3];
    #pragma unroll
    for (int r = 0; r < 3; r++) {
        float w = (m0[c*3+r] > 0.f) ? m0[c*3+r] + log1pf(expf(-m0[c*3+r])) : log1pf(expf(m0[c*3+r]));
        v[r] = fmaf(w, x, b0[c*3+r]);
        v[r] = fmaf(tanhf(f0[c*3+r]), tanhf(v[r]), v[r]);
    }
    #pragma unroll
    for (int r = 0; r < 3; r++) {
        u[r] = b1[c*3+r];
        #pragma unroll
        for (int k = 0; k < 3; k++) {
            float m = m1[c*9 + r*3 + k];
            float w = (m > 0.f) ? m + log1pf(expf(-m)) : log1pf(expf(m));
            u[r] = fmaf(w, v[k], u[r]);
        }
        u[r] = fmaf(tanhf(f1[c*3+r]), tanhf(u[r]), u[r]);
    }
    #pragma unroll
    for (int r = 0; r < 3; r++) {
        v[r] = b2[c*3+r];
        #pragma unroll
        for (int k = 0; k < 3; k++) {
            float m = m2[c*9 + r*3 + k];
            float w = (m > 0.f) ? m + log1pf(expf(-m)) : log1pf(expf(m));
            v[r] = fmaf(w, u[k], v[r]);
        }
        v[r] = fmaf(tanhf(f2[c*3+r]), tanhf(v[r]), v[r]);
    }
    float l = b3[c];
    #pragma unroll
    for (int k = 0; k < 3; k++) {
        float m = m3[c*3+k];
        float w = (m > 0.f) ? m + log1pf(expf(-m)) : log1pf(expf(m));
        l = fmaf(w, v[k], l);
    }
    return 1.f / (1.f + expf(-l));
}

__device__ __forceinline__ void affine_quad(float4 zv, float4 p, float4& zh, float4& lk) {
    // p = {a, d, K=e^a, h=0.5a}
    #pragma unroll
    for (int j = 0; j < 4; j++) {
        float x  = rintf((&zv.x)[j]);                  // round half-to-even == jnp.round
        float t  = fmaf(p.x, x, p.y);
        float E  = __expf(-(t + p.w));                 // e^{-(t+h)}
        // up - lo = E*(K-1) / ((1+E)*(1+E*K)) : single fast divide, no cancellation
        float num = E * (p.z - 1.f);
        float den = (1.f + E) * fmaf(E, p.z, 1.f);
        (&zh.x)[j] = x;
        (&lk.x)[j] = fmaxf(__fdividef(num, den), 1e-9f);
    }
}

__global__ void __launch_bounds__(256, 6) fp_fused_kernel(
        const float4* __restrict__ z, float* __restrict__ out,
        const float* __restrict__ m0, const float* __restrict__ m1,
        const float* __restrict__ m2, const float* __restrict__ m3,
        const float* __restrict__ b0, const float* __restrict__ b1,
        const float* __restrict__ b2, const float* __restrict__ b3,
        const float* __restrict__ f0, const float* __restrict__ f1,
        const float* __restrict__ f2) {
    __shared__ float4 s_ad[NCH];   // {a, d, exp(a), 0.5a}

    int tid = threadIdx.x;

    // ---- per-block affine table (one channel per thread), L2-resident params ----
    int nz = 0;
    if (tid < NCH) {
        int c = tid;
        float w0[3], W1[9], W2[9], w3[3];
        #pragma unroll
        for (int i = 0; i < 3; i++) w0[i] = softplus_fast(m0[c * 3 + i]);
        #pragma unroll
        for (int i = 0; i < 9; i++) W1[i] = softplus_fast(m1[c * 9 + i]);
        #pragma unroll
        for (int i = 0; i < 9; i++) W2[i] = softplus_fast(m2[c * 9 + i]);
        #pragma unroll
        for (int i = 0; i < 3; i++) w3[i] = softplus_fast(m3[c * 3 + i]);

        #pragma unroll
        for (int i = 0; i < 3; i++) nz |= (f0[c * 3 + i] != 0.f);
        #pragma unroll
        for (int i = 0; i < 3; i++) nz |= (f1[c * 3 + i] != 0.f);
        #pragma unroll
        for (int i = 0; i < 3; i++) nz |= (f2[c * 3 + i] != 0.f);

        float va[3], vd[3];
        #pragma unroll
        for (int i = 0; i < 3; i++) { va[i] = w0[i]; vd[i] = b0[c * 3 + i]; }

        float ta[3], td[3];
        #pragma unroll
        for (int r = 0; r < 3; r++) {
            ta[r] = W1[r*3+0]*va[0] + W1[r*3+1]*va[1] + W1[r*3+2]*va[2];
            td[r] = W1[r*3+0]*vd[0] + W1[r*3+1]*vd[1] + W1[r*3+2]*vd[2] + b1[c*3+r];
        }
        #pragma unroll
        for (int r = 0; r < 3; r++) {
            va[r] = W2[r*3+0]*ta[0] + W2[r*3+1]*ta[1] + W2[r*3+2]*ta[2];
            vd[r] = W2[r*3+0]*td[0] + W2[r*3+1]*td[1] + W2[r*3+2]*td[2] + b2[c*3+r];
        }
        float a = w3[0]*va[0] + w3[1]*va[1] + w3[2]*va[2];
        float d = w3[0]*vd[0] + w3[1]*vd[1] + w3[2]*vd[2] + b3[c];

        s_ad[c] = make_float4(a, d, __expf(a), 0.5f * a);
    }
    int flag = __syncthreads_or(nz);   // barrier also publishes s_ad

    float4* out_zh = reinterpret_cast<float4*>(out);
    float4* out_lk = reinterpret_cast<float4*>(out + NELEM);

    // ---- streaming loop (R5-proven structure) ----
    for (int base = blockIdx.x * 512 + tid; base < N4; base += CHUNK) {
        int i0 = base;
        int i1 = base + 256;          // always < N4 (N4 % 512 == 0)
        int c0 = (i0 >> 10) % NCH;    // 1024 float4 per (b,c) plane
        int c1 = (i1 >> 10) % NCH;    // warp-uniform -> smem broadcast

        float4 zv0 = __ldcs(z + i0);
        float4 zv1 = __ldcs(z + i1);
        float4 zh0, lk0, zh1, lk1;

        if (flag == 0) {
            affine_quad(zv0, s_ad[c0], zh0, lk0);
            affine_quad(zv1, s_ad[c1], zh1, lk1);
        } else {
            #pragma unroll
            for (int j = 0; j < 4; j++) {
                float x0 = rintf((&zv0.x)[j]);
                (&zh0.x)[j] = x0;
                (&lk0.x)[j] = fmaxf(cdf_raw(c0, x0+0.5f, m0,m1,m2,m3,b0,b1,b2,b3,f0,f1,f2)
                                  - cdf_raw(c0, x0-0.5f, m0,m1,m2,m3,b0,b1,b2,b3,f0,f1,f2), 1e-9f);
                float x1 = rintf((&zv1.x)[j]);
                (&zh1.x)[j] = x1;
                (&lk1.x)[j] = fmaxf(cdf_raw(c1, x1+0.5f, m0,m1,m2,m3,b0,b1,b2,b3,f0,f1,f2)
                                  - cdf_raw(c1, x1-0.5f, m0,m1,m2,m3,b0,b1,b2,b3,f0,f1,f2), 1e-9f);
            }
        }

        __stcs(out_zh + i0, zh0);
        __stcs(out_zh + i1, zh1);
        __stcs(out_lk + i0, lk0);
        __stcs(out_lk + i1, lk1);
    }
}

extern "C" void kernel_launch(void* const* d_in, const int* in_sizes, int n_in,
                              void* d_out, int out_size) {
    const float* z  = (const float*)d_in[0];
    const float* m0 = (const float*)d_in[1];
    const float* m1 = (const float*)d_in[2];
    const float* m2 = (const float*)d_in[3];
    const float* m3 = (const float*)d_in[4];
    const float* b0 = (const float*)d_in[5];
    const float* b1 = (const float*)d_in[6];
    const float* b2 = (const float*)d_in[7];
    const float* b3 = (const float*)d_in[8];
    const float* f0 = (const float*)d_in[9];
    const float* f1 = (const float*)d_in[10];
    const float* f2 = (const float*)d_in[11];

    fp_fused_kernel<<<GRID_MAIN, 256>>>((const float4*)z, (float*)d_out,
                                        m0, m1, m2, m3, b0, b1, b2, b3, f0, f1, f2);
}